// round 14
// baseline (speedup 1.0000x reference)
#include <cuda_runtime.h>
#include <cuda_fp16.h>
#include <cstdint>

#define ALPHA 0.2f
#define LOG2E 1.4426950408889634f

// Scratch: max BT = 128 slices. g_Wh layout: [row(65536)][d(128)], fp16.
// g_es/g_ed are PRE-SCALED by log2(e).
__device__ __half g_Wh[128 * 512 * 128];
__device__ float g_es[128 * 512];
__device__ float g_ed[128 * 512];
__device__ uint32_t g_adjmask[512 * 16];   // row i, word w = bits j=32w..32w+31

// ---------------------------------------------------------------------------
// helpers
// ---------------------------------------------------------------------------
__device__ __forceinline__ float ex2(float x) {
    float r;
    asm("ex2.approx.f32 %0, %1;" : "=f"(r) : "f"(x));
    return r;
}

__device__ __forceinline__ void mma_f16(float* d, const uint32_t* a, const uint32_t* b) {
    asm volatile(
        "mma.sync.aligned.m16n8k16.row.col.f32.f16.f16.f32 "
        "{%0,%1,%2,%3}, {%4,%5,%6,%7}, {%8,%9}, {%0,%1,%2,%3};"
        : "+f"(d[0]), "+f"(d[1]), "+f"(d[2]), "+f"(d[3])
        : "r"(a[0]), "r"(a[1]), "r"(a[2]), "r"(a[3]), "r"(b[0]), "r"(b[1]));
}

#define LDSM_X4(r, addr) \
    asm volatile("ldmatrix.sync.aligned.m8n8.x4.shared.b16 {%0,%1,%2,%3}, [%4];" \
        : "=r"((r)[0]), "=r"((r)[1]), "=r"((r)[2]), "=r"((r)[3]) : "r"(addr))

#define LDSM_X4_T(r, addr) \
    asm volatile("ldmatrix.sync.aligned.m8n8.x4.trans.shared.b16 {%0,%1,%2,%3}, [%4];" \
        : "=r"((r)[0]), "=r"((r)[1]), "=r"((r)[2]), "=r"((r)[3]) : "r"(addr))

static constexpr int SPH = 68;            // u32 (half2) row stride for MMA tiles
static constexpr int BUF = 128 * SPH;     // u32 per 128-row tile
static constexpr int BUFP = 64 * SPH;     // u32 per 64-row tile

// ---------------------------------------------------------------------------
// Kernel A: Wh = h @ W via m16n8k16 fp16. 64 rows / 256 threads per CTA,
// 2 CTAs/SM. Folded adjmask (grid-strided rows, 2 ballots each).
// ---------------------------------------------------------------------------
static constexpr int SMEM_WH = (BUFP + BUF + 384) * 4;   // 53,760 B

__global__ __launch_bounds__(256, 2)
void gat_wh_mma(const float* __restrict__ h, const float* __restrict__ W,
                const float* __restrict__ a, const int* __restrict__ adj) {
    extern __shared__ uint32_t smu[];
    uint32_t* hs = smu;                  // [row 64][k half2 34] stride 68
    uint32_t* Ws = smu + BUFP;           // [k 128][d half2 34] stride 68
    float* a_sh  = (float*)(smu + BUFP + BUF);
    float* es_sm = a_sh + 256;
    float* ed_sm = es_sm + 64;

    int t = threadIdx.x, w = t >> 5, l = t & 31;
    long brow = (long)blockIdx.x * 64;

    // Folded adjmask: one row per CTA iteration, 2 ballots (512 cols).
    for (int r = blockIdx.x; r < 512; r += gridDim.x) {
        int v0 = adj[r * 512 + t];
        unsigned m0 = __ballot_sync(0xffffffffu, v0 > 0);
        if (l == 0) g_adjmask[r * 16 + w] = m0;
        int v1 = adj[r * 512 + 256 + t];
        unsigned m1 = __ballot_sync(0xffffffffu, v1 > 0);
        if (l == 0) g_adjmask[r * 16 + 8 + w] = m1;
    }

    a_sh[t] = a[t & 255];
    if (t < 128) { es_sm[t & 63] = 0.f; }   // es_sm[64] + ed_sm[64] contiguous
    if (t < 128) { ed_sm[t & 63] = 0.f; }

    // Stage h tile (64 x 128 fp32 -> fp16) and W (128 x 128, [k][d]).
    {
        const float4* hg = (const float4*)(h + brow * 128);
#pragma unroll
        for (int m = 0; m < 8; m++) {
            int idx = t + m * 256;               // 0..2047
            int r = idx >> 5, c4 = idx & 31;
            float4 v = hg[idx];
            uint2 st;
            __half2 p0 = __floats2half2_rn(v.x, v.y);
            __half2 p1 = __floats2half2_rn(v.z, v.w);
            st.x = *(uint32_t*)&p0; st.y = *(uint32_t*)&p1;
            *(uint2*)&hs[r * SPH + 2 * c4] = st;
        }
        const float4* Wg = (const float4*)W;
#pragma unroll
        for (int m = 0; m < 16; m++) {
            int idx = t + m * 256;               // 0..4095
            int r = idx >> 5, c4 = idx & 31;
            float4 wv = Wg[idx];
            uint2 st;
            __half2 q0 = __floats2half2_rn(wv.x, wv.y);
            __half2 q1 = __floats2half2_rn(wv.z, wv.w);
            st.x = *(uint32_t*)&q0; st.y = *(uint32_t*)&q1;
            *(uint2*)&Ws[r * SPH + 2 * c4] = st;
        }
    }
    __syncthreads();

    int wm = w >> 2, wn = w & 3;
    int gid = l >> 2, tig = l & 3;

    uint32_t hs_addr, ws_addr;
    asm("{ .reg .u64 tt; cvta.to.shared.u64 tt, %1; cvt.u32.u64 %0, tt; }"
        : "=r"(hs_addr) : "l"((const void*)hs));
    asm("{ .reg .u64 tt; cvta.to.shared.u64 tt, %1; cvt.u32.u64 %0, tt; }"
        : "=r"(ws_addr) : "l"((const void*)Ws));

    uint32_t a_lane = (uint32_t)((wm * 32 + (l & 7) + 8 * ((l >> 3) & 1)) * SPH
                                 + 4 * (l >> 4)) * 4u;
    uint32_t b_lane = (uint32_t)(((l & 7) + 8 * ((l >> 3) & 1)) * SPH) * 4u
                    + (uint32_t)(wn * 32 + 8 * (l >> 4)) * 2u;

    float acc[2][4][4];
#pragma unroll
    for (int mt = 0; mt < 2; mt++)
#pragma unroll
        for (int nt = 0; nt < 4; nt++)
#pragma unroll
            for (int e = 0; e < 4; e++) acc[mt][nt][e] = 0.f;

    uint32_t pa = hs_addr + a_lane;
    uint32_t ba = ws_addr + b_lane;
    const uint32_t mt_step = 16 * SPH * 4;
#pragma unroll
    for (int ks = 0; ks < 8; ks++) {
        uint32_t A0[4], A1[4], B0[4], B1[4];
        LDSM_X4(A0, pa);
        LDSM_X4(A1, pa + mt_step);
        LDSM_X4_T(B0, ba);
        LDSM_X4_T(B1, ba + 32);          // +16 d halves
        uint32_t* Af[2] = {A0, A1};
        uint32_t Bf[4][2] = {{B0[0], B0[1]}, {B0[2], B0[3]},
                             {B1[0], B1[1]}, {B1[2], B1[3]}};
#pragma unroll
        for (int mt = 0; mt < 2; mt++)
#pragma unroll
            for (int nt = 0; nt < 4; nt++)
                mma_f16(acc[mt][nt], Af[mt], Bf[nt]);
        pa += 32;                        // k += 16 halves
        ba += 16 * SPH * 4;              // k rows += 16
    }

#pragma unroll
    for (int mt = 0; mt < 2; mt++) {
        int r0 = wm * 32 + mt * 16 + gid;
        int r1 = r0 + 8;
        float s0 = 0.f, d0 = 0.f, s1 = 0.f, d1 = 0.f;
#pragma unroll
        for (int nt = 0; nt < 4; nt++) {
            int col = wn * 32 + nt * 8 + 2 * tig;
            __half2 v0 = __floats2half2_rn(acc[mt][nt][0], acc[mt][nt][1]);
            __half2 v1 = __floats2half2_rn(acc[mt][nt][2], acc[mt][nt][3]);
            *(__half2*)(g_Wh + (brow + r0) * 128 + col) = v0;
            *(__half2*)(g_Wh + (brow + r1) * 128 + col) = v1;
            s0 += acc[mt][nt][0] * a_sh[col] + acc[mt][nt][1] * a_sh[col + 1];
            d0 += acc[mt][nt][0] * a_sh[128 + col] + acc[mt][nt][1] * a_sh[128 + col + 1];
            s1 += acc[mt][nt][2] * a_sh[col] + acc[mt][nt][3] * a_sh[col + 1];
            d1 += acc[mt][nt][2] * a_sh[128 + col] + acc[mt][nt][3] * a_sh[128 + col + 1];
        }
#pragma unroll
        for (int o = 1; o <= 2; o <<= 1) {
            s0 += __shfl_xor_sync(0xffffffffu, s0, o);
            d0 += __shfl_xor_sync(0xffffffffu, d0, o);
            s1 += __shfl_xor_sync(0xffffffffu, s1, o);
            d1 += __shfl_xor_sync(0xffffffffu, d1, o);
        }
        if (tig == 0) {
            atomicAdd(es_sm + r0, s0); atomicAdd(ed_sm + r0, d0);
            atomicAdd(es_sm + r1, s1); atomicAdd(ed_sm + r1, d1);
        }
    }
    __syncthreads();
    if (t < 64) {
        g_es[brow + t] = es_sm[t] * LOG2E;   // pre-scaled for ex2
        g_ed[brow + t] = ed_sm[t] * LOG2E;
    }
}

// ---------------------------------------------------------------------------
// Kernel B: 64 i-rows per CTA, 256 threads / 8 warps, 2 CTAs/SM.
// Double-buffered Ps(64)/Bs(128); role-alternating warps; cp.async.cg B
// staging; mask+ed in smem; ex2.approx; ROW SUMS VIA ONES-MMA (no lsum chain).
// ---------------------------------------------------------------------------
static constexpr int MASK_OFF = 2 * BUFP + 2 * BUF;       // u32 idx
static constexpr int ED_OFF   = MASK_OFF + 1024;          // 16 quarters x 36 fl
static constexpr int SMEM_ATTN = (ED_OFF + 16 * 36) * 4;  // ~111 KB

__global__ __launch_bounds__(256, 2)
void gat_attn_mma(float* __restrict__ out) {
    extern __shared__ uint32_t smu[];
    uint32_t* Ps = smu;                   // 2 x [i 64][k half2 34] stride 68
    uint32_t* Bs = smu + 2 * BUFP;        // 2 x [k 128][d half2 34] stride 68
    uint32_t* mask_sm = smu + MASK_OFF;   // [i 64][word 16]
    float* ed_sm = (float*)(smu + ED_OFF);// 16 quarters x (32 + 4 pad)

    int t = threadIdx.x;
    int w = t >> 5;
    int l = t & 31;
    int bt = blockIdx.x >> 3;
    int ibase = (blockIdx.x & 7) * 64;
    long rowbase = (long)bt * 512;

    // Preload mask (64 rows x 16 words) and ed (512 fl, padded quarters).
#pragma unroll
    for (int m = 0; m < 4; m++) {
        int idx = t + m * 256;
        mask_sm[idx] = g_adjmask[ibase * 16 + idx];
    }
#pragma unroll
    for (int m = 0; m < 2; m++) {
        int f = t + m * 256;
        ed_sm[(f >> 5) * 36 + (f & 31)] = g_ed[rowbase + f];
    }

    // P-build mapping: thread t -> row t>>2 (0..63), j quarter (t&3)
    int i_row = t >> 2;
    int kkb = (t & 3) * 16;
    float es_i = g_es[rowbase + ibase + i_row];   // pre-scaled by log2e

    // MMA mapping: 8 warps, wm = w>>2 (0..1), wn = w&3
    int wm = w >> 2, wn = w & 3;
    int gid = l >> 2, tig = l & 3;

    const __half* Whb = g_Wh + rowbase * 128;

    uint32_t ps_addr, bs_addr;
    asm("{ .reg .u64 tt; cvta.to.shared.u64 tt, %1; cvt.u32.u64 %0, tt; }"
        : "=r"(ps_addr) : "l"((const void*)Ps));
    asm("{ .reg .u64 tt; cvta.to.shared.u64 tt, %1; cvt.u32.u64 %0, tt; }"
        : "=r"(bs_addr) : "l"((const void*)Bs));

    uint32_t a_lane = (uint32_t)((wm * 32 + (l & 7) + 8 * ((l >> 3) & 1)) * SPH
                                 + 4 * (l >> 4)) * 4u;
    uint32_t b_lane = (uint32_t)(((l & 7) + 8 * ((l >> 3) & 1)) * SPH) * 4u
                    + (uint32_t)(wn * 32 + 8 * (l >> 4)) * 2u;

    float acc[2][4][4];
    float acc_l[2][4];                    // ones-MMA row sums
#pragma unroll
    for (int mt = 0; mt < 2; mt++) {
#pragma unroll
        for (int nt = 0; nt < 4; nt++)
#pragma unroll
            for (int e = 0; e < 4; e++) acc[mt][nt][e] = 0.f;
#pragma unroll
        for (int e = 0; e < 4; e++) acc_l[mt][e] = 0.f;
    }

    auto stage_B = [&](int jt, int buf) {
#pragma unroll
        for (int m = 0; m < 8; m++) {
            int idx = t + m * 256;
            int j = idx >> 4, ch = idx & 15;
            uint32_t dst = bs_addr + (uint32_t)(buf * BUF * 4 + j * SPH * 4 + ch * 16);
            const void* src = Whb + (long)(jt * 128 + j) * 128 + ch * 8;
            asm volatile("cp.async.cg.shared.global [%0], [%1], 16;" :: "r"(dst), "l"(src));
        }
        asm volatile("cp.async.commit_group;" ::: "memory");
    };

    auto build_P = [&](int jt, int buf) {
        uint32_t* Pb = Ps + buf * BUFP;
        uint32_t mask = mask_sm[i_row * 16 + jt * 4 + (t & 3)];
        const float4* edp = (const float4*)(ed_sm + (jt * 4 + (t & 3)) * 36);
#pragma unroll
        for (int c = 0; c < 8; c++) {
            float4 edv = edp[c];
            float x, p0, p1, p2, p3;
            x = es_i + edv.x; x = fmaxf(x, ALPHA * x); p0 = (mask >> (4 * c))     & 1 ? ex2(x) : 0.f;
            x = es_i + edv.y; x = fmaxf(x, ALPHA * x); p1 = (mask >> (4 * c + 1)) & 1 ? ex2(x) : 0.f;
            x = es_i + edv.z; x = fmaxf(x, ALPHA * x); p2 = (mask >> (4 * c + 2)) & 1 ? ex2(x) : 0.f;
            x = es_i + edv.w; x = fmaxf(x, ALPHA * x); p3 = (mask >> (4 * c + 3)) & 1 ? ex2(x) : 0.f;
            __half2 h01 = __float22half2_rn(make_float2(p0, p1));
            __half2 h23 = __float22half2_rn(make_float2(p2, p3));
            uint2 st;
            st.x = *(uint32_t*)&h01;
            st.y = *(uint32_t*)&h23;
            *(uint2*)&Pb[i_row * SPH + kkb + 2 * c] = st;
        }
    };

    auto do_mma = [&](int buf) {
        uint32_t pa = ps_addr + (uint32_t)(buf * BUFP * 4) + a_lane;
        uint32_t ba = bs_addr + (uint32_t)(buf * BUF * 4) + b_lane;
        const uint32_t mt_step = 16 * SPH * 4;
        const uint32_t onesb[2] = {0x3C003C00u, 0x3C003C00u};   // half2(1,1)
#pragma unroll
        for (int ks = 0; ks < 8; ks++) {
            uint32_t A0[4], A1[4], B0[4], B1[4];
            LDSM_X4(A0, pa);
            LDSM_X4(A1, pa + mt_step);
            LDSM_X4_T(B0, ba);
            LDSM_X4_T(B1, ba + 32);
            uint32_t* Af[2] = {A0, A1};
            uint32_t Bf[4][2] = {{B0[0], B0[1]}, {B0[2], B0[3]},
                                 {B1[0], B1[1]}, {B1[2], B1[3]}};
#pragma unroll
            for (int mt = 0; mt < 2; mt++) {
#pragma unroll
                for (int nt = 0; nt < 4; nt++)
                    mma_f16(acc[mt][nt], Af[mt], Bf[nt]);
                mma_f16(acc_l[mt], Af[mt], onesb);   // row sums
            }
            pa += 32;               // k += 16 halves
            ba += 16 * SPH * 4;     // k rows += 16
        }
    };

    stage_B(0, 0);
    __syncthreads();   // mask_sm/ed_sm visible before first build_P

    build_P(0, 0);
    asm volatile("cp.async.wait_group 0;" ::: "memory");
    __syncthreads();

    for (int jt = 0; jt < 4; jt++) {
        int buf = jt & 1, nbuf = buf ^ 1;
        if (jt < 3) stage_B(jt + 1, nbuf);
        if (w & 1) {
            if (jt < 3) build_P(jt + 1, nbuf);
            do_mma(buf);
        } else {
            do_mma(buf);
            if (jt < 3) build_P(jt + 1, nbuf);
        }
        asm volatile("cp.async.wait_group 0;" ::: "memory");
        __syncthreads();
    }

    // Epilogue: out = acc / l  (l from ones-MMA: acc_l[mt][0]=row gid, [2]=+8).
#pragma unroll
    for (int mt = 0; mt < 2; mt++) {
        int rb = wm * 32 + mt * 16;
        float inv0 = 1.f / acc_l[mt][0];
        float inv1 = 1.f / acc_l[mt][2];
        long row0 = rowbase + ibase + rb + gid;
        long row1 = row0 + 8;
#pragma unroll
        for (int nt = 0; nt < 4; nt++) {
            int col = wn * 32 + nt * 8 + 2 * tig;
            *(float2*)(out + row0 * 128 + col) =
                make_float2(acc[mt][nt][0] * inv0, acc[mt][nt][1] * inv0);
            *(float2*)(out + row1 * 128 + col) =
                make_float2(acc[mt][nt][2] * inv1, acc[mt][nt][3] * inv1);
        }
    }
}

extern "C" void kernel_launch(void* const* d_in, const int* in_sizes, int n_in,
                              void* d_out, int out_size) {
    const float* h   = (const float*)d_in[0];
    const int*   adj = (const int*)d_in[1];
    const float* W   = (const float*)d_in[2];
    const float* a   = (const float*)d_in[3];
    float* out = (float*)d_out;

    int BT = in_sizes[0] / (512 * 128);
    if (BT > 128) BT = 128;

    cudaFuncSetAttribute(gat_wh_mma,
                         cudaFuncAttributeMaxDynamicSharedMemorySize, SMEM_WH);
    cudaFuncSetAttribute(gat_attn_mma,
                         cudaFuncAttributeMaxDynamicSharedMemorySize, SMEM_ATTN);

    gat_wh_mma<<<BT * 8, 256, SMEM_WH>>>(h, W, a, adj);
    gat_attn_mma<<<BT * 8, 256, SMEM_ATTN>>>(out);
}

// round 15
// speedup vs baseline: 1.0253x; 1.0253x over previous
#include <cuda_runtime.h>
#include <cuda_fp16.h>
#include <cstdint>

#define ALPHA 0.2f
#define LOG2E 1.4426950408889634f

// Scratch: max BT = 128 slices. g_Wh layout: [row(65536)][d(128)], fp16.
// g_es/g_ed are PRE-SCALED by log2(e).
__device__ __half g_Wh[128 * 512 * 128];
__device__ float g_es[128 * 512];
__device__ float g_ed[128 * 512];
__device__ uint32_t g_adjmask[512 * 16];   // row i, word w = bits j=32w..32w+31

// ---------------------------------------------------------------------------
// helpers
// ---------------------------------------------------------------------------
__device__ __forceinline__ float ex2(float x) {
    float r;
    asm("ex2.approx.f32 %0, %1;" : "=f"(r) : "f"(x));
    return r;
}

__device__ __forceinline__ void mma_f16(float* d, const uint32_t* a, const uint32_t* b) {
    asm volatile(
        "mma.sync.aligned.m16n8k16.row.col.f32.f16.f16.f32 "
        "{%0,%1,%2,%3}, {%4,%5,%6,%7}, {%8,%9}, {%0,%1,%2,%3};"
        : "+f"(d[0]), "+f"(d[1]), "+f"(d[2]), "+f"(d[3])
        : "r"(a[0]), "r"(a[1]), "r"(a[2]), "r"(a[3]), "r"(b[0]), "r"(b[1]));
}

#define LDSM_X4(r, addr) \
    asm volatile("ldmatrix.sync.aligned.m8n8.x4.shared.b16 {%0,%1,%2,%3}, [%4];" \
        : "=r"((r)[0]), "=r"((r)[1]), "=r"((r)[2]), "=r"((r)[3]) : "r"(addr))

#define LDSM_X4_T(r, addr) \
    asm volatile("ldmatrix.sync.aligned.m8n8.x4.trans.shared.b16 {%0,%1,%2,%3}, [%4];" \
        : "=r"((r)[0]), "=r"((r)[1]), "=r"((r)[2]), "=r"((r)[3]) : "r"(addr))

static constexpr int SPH = 68;            // u32 (half2) row stride for MMA tiles
static constexpr int BUF = 128 * SPH;     // u32 per 128-row tile
static constexpr int BUFP = 64 * SPH;     // u32 per 64-row tile

// ---------------------------------------------------------------------------
// Kernel A (R12 config): Wh = h @ W via m16n8k16 fp16, K=128 single-shot.
// 128 rows / 512 threads per CTA. Folded adjmask (grid-strided rows).
// ---------------------------------------------------------------------------
static constexpr int SMEM_WH = (2 * BUF + 512) * 4;   // 71,680 B

__global__ __launch_bounds__(512, 1)
void gat_wh_mma(const float* __restrict__ h, const float* __restrict__ W,
                const float* __restrict__ a, const int* __restrict__ adj) {
    extern __shared__ uint32_t smu[];
    uint32_t* hs = smu;                  // [row 128][k half2 34] stride 68
    uint32_t* Ws = smu + BUF;            // [k 128][d half2 34] stride 68
    float* a_sh  = (float*)(smu + 2 * BUF);
    float* es_sm = a_sh + 256;
    float* ed_sm = es_sm + 128;

    int t = threadIdx.x, w = t >> 5, l = t & 31;
    long brow = (long)blockIdx.x * 128;

    // Folded adjmask: CTA handles adj rows blockIdx.x, +gridDim.x, ...
    for (int r = blockIdx.x; r < 512; r += gridDim.x) {
        int v = adj[r * 512 + t];
        unsigned m = __ballot_sync(0xffffffffu, v > 0);
        if (l == 0) g_adjmask[r * 16 + w] = m;
    }

    if (t < 256) a_sh[t] = a[t];
    if (t < 128) { es_sm[t] = 0.f; ed_sm[t] = 0.f; }

    {
        const float4* hg = (const float4*)(h + brow * 128);
        const float4* Wg = (const float4*)W;
#pragma unroll
        for (int m = 0; m < 8; m++) {
            int idx = t + m * 512;               // 0..4095
            int r = idx >> 5, c4 = idx & 31;
            float4 v = hg[idx];
            uint2 st;
            __half2 p0 = __floats2half2_rn(v.x, v.y);
            __half2 p1 = __floats2half2_rn(v.z, v.w);
            st.x = *(uint32_t*)&p0; st.y = *(uint32_t*)&p1;
            *(uint2*)&hs[r * SPH + 2 * c4] = st;

            float4 wv = Wg[idx];
            __half2 q0 = __floats2half2_rn(wv.x, wv.y);
            __half2 q1 = __floats2half2_rn(wv.z, wv.w);
            st.x = *(uint32_t*)&q0; st.y = *(uint32_t*)&q1;
            *(uint2*)&Ws[r * SPH + 2 * c4] = st;
        }
    }
    __syncthreads();

    int wm = w >> 2, wn = w & 3;
    int gid = l >> 2, tig = l & 3;

    uint32_t hs_addr, ws_addr;
    asm("{ .reg .u64 tt; cvta.to.shared.u64 tt, %1; cvt.u32.u64 %0, tt; }"
        : "=r"(hs_addr) : "l"((const void*)hs));
    asm("{ .reg .u64 tt; cvta.to.shared.u64 tt, %1; cvt.u32.u64 %0, tt; }"
        : "=r"(ws_addr) : "l"((const void*)Ws));

    uint32_t a_lane = (uint32_t)((wm * 32 + (l & 7) + 8 * ((l >> 3) & 1)) * SPH
                                 + 4 * (l >> 4)) * 4u;
    uint32_t b_lane = (uint32_t)(((l & 7) + 8 * ((l >> 3) & 1)) * SPH) * 4u
                    + (uint32_t)(wn * 32 + 8 * (l >> 4)) * 2u;

    float acc[2][4][4];
#pragma unroll
    for (int mt = 0; mt < 2; mt++)
#pragma unroll
        for (int nt = 0; nt < 4; nt++)
#pragma unroll
            for (int e = 0; e < 4; e++) acc[mt][nt][e] = 0.f;

    uint32_t pa = hs_addr + a_lane;
    uint32_t ba = ws_addr + b_lane;
    const uint32_t mt_step = 16 * SPH * 4;
#pragma unroll
    for (int ks = 0; ks < 8; ks++) {
        uint32_t A0[4], A1[4], B0[4], B1[4];
        LDSM_X4(A0, pa);
        LDSM_X4(A1, pa + mt_step);
        LDSM_X4_T(B0, ba);
        LDSM_X4_T(B1, ba + 32);          // +16 d halves
        uint32_t* Af[2] = {A0, A1};
        uint32_t Bf[4][2] = {{B0[0], B0[1]}, {B0[2], B0[3]},
                             {B1[0], B1[1]}, {B1[2], B1[3]}};
#pragma unroll
        for (int mt = 0; mt < 2; mt++)
#pragma unroll
            for (int nt = 0; nt < 4; nt++)
                mma_f16(acc[mt][nt], Af[mt], Bf[nt]);
        pa += 32;                        // k += 16 halves
        ba += 16 * SPH * 4;              // k rows += 16
    }

#pragma unroll
    for (int mt = 0; mt < 2; mt++) {
        int r0 = wm * 32 + mt * 16 + gid;
        int r1 = r0 + 8;
        float s0 = 0.f, d0 = 0.f, s1 = 0.f, d1 = 0.f;
#pragma unroll
        for (int nt = 0; nt < 4; nt++) {
            int col = wn * 32 + nt * 8 + 2 * tig;
            __half2 v0 = __floats2half2_rn(acc[mt][nt][0], acc[mt][nt][1]);
            __half2 v1 = __floats2half2_rn(acc[mt][nt][2], acc[mt][nt][3]);
            *(__half2*)(g_Wh + (brow + r0) * 128 + col) = v0;
            *(__half2*)(g_Wh + (brow + r1) * 128 + col) = v1;
            s0 += acc[mt][nt][0] * a_sh[col] + acc[mt][nt][1] * a_sh[col + 1];
            d0 += acc[mt][nt][0] * a_sh[128 + col] + acc[mt][nt][1] * a_sh[128 + col + 1];
            s1 += acc[mt][nt][2] * a_sh[col] + acc[mt][nt][3] * a_sh[col + 1];
            d1 += acc[mt][nt][2] * a_sh[128 + col] + acc[mt][nt][3] * a_sh[128 + col + 1];
        }
#pragma unroll
        for (int o = 1; o <= 2; o <<= 1) {
            s0 += __shfl_xor_sync(0xffffffffu, s0, o);
            d0 += __shfl_xor_sync(0xffffffffu, d0, o);
            s1 += __shfl_xor_sync(0xffffffffu, s1, o);
            d1 += __shfl_xor_sync(0xffffffffu, d1, o);
        }
        if (tig == 0) {
            atomicAdd(es_sm + r0, s0); atomicAdd(ed_sm + r0, d0);
            atomicAdd(es_sm + r1, s1); atomicAdd(ed_sm + r1, d1);
        }
    }
    __syncthreads();
    if (t < 128) {
        g_es[brow + t] = es_sm[t] * LOG2E;   // pre-scaled for ex2
        g_ed[brow + t] = ed_sm[t] * LOG2E;
    }
}

// ---------------------------------------------------------------------------
// Kernel B (R12 + B-fragment prefetch): 64 i-rows per CTA, 256 threads,
// 2 CTAs/SM. Double-buffered Ps/Bs; role-alternating warps; cp.async.cg B
// staging; mask+ed in smem; ex2.approx; scalar lsum; B LDSM pipelined 1 ahead.
// ---------------------------------------------------------------------------
static constexpr int MASK_OFF = 2 * BUFP + 2 * BUF;       // u32 idx
static constexpr int ED_OFF   = MASK_OFF + 1024;          // 16 quarters x 36 fl
static constexpr int L_OFF    = ED_OFF + 16 * 36;
static constexpr int SMEM_ATTN = (L_OFF + 64) * 4;        // ~111 KB

__global__ __launch_bounds__(256, 2)
void gat_attn_mma(float* __restrict__ out) {
    extern __shared__ uint32_t smu[];
    uint32_t* Ps = smu;                   // 2 x [i 64][k half2 34] stride 68
    uint32_t* Bs = smu + 2 * BUFP;        // 2 x [k 128][d half2 34] stride 68
    uint32_t* mask_sm = smu + MASK_OFF;   // [i 64][word 16]
    float* ed_sm = (float*)(smu + ED_OFF);// 16 quarters x (32 + 4 pad)
    float* l_sh = (float*)(smu + L_OFF);

    int t = threadIdx.x;
    int w = t >> 5;
    int l = t & 31;
    int bt = blockIdx.x >> 3;
    int ibase = (blockIdx.x & 7) * 64;
    long rowbase = (long)bt * 512;

    if (t < 64) l_sh[t] = 0.f;

    // Preload mask (64 rows x 16 words) and ed (512 fl, padded quarters).
#pragma unroll
    for (int m = 0; m < 4; m++) {
        int idx = t + m * 256;
        mask_sm[idx] = g_adjmask[ibase * 16 + idx];
    }
#pragma unroll
    for (int m = 0; m < 2; m++) {
        int f = t + m * 256;
        ed_sm[(f >> 5) * 36 + (f & 31)] = g_ed[rowbase + f];
    }

    // P-build mapping: thread t -> row t>>2 (0..63), j quarter (t&3)
    int i_row = t >> 2;
    int kkb = (t & 3) * 16;
    float es_i = g_es[rowbase + ibase + i_row];   // pre-scaled by log2e

    // MMA mapping: 8 warps, wm = w>>2 (0..1), wn = w&3
    int wm = w >> 2, wn = w & 3;
    int gid = l >> 2, tig = l & 3;

    const __half* Whb = g_Wh + rowbase * 128;

    uint32_t ps_addr, bs_addr;
    asm("{ .reg .u64 tt; cvta.to.shared.u64 tt, %1; cvt.u32.u64 %0, tt; }"
        : "=r"(ps_addr) : "l"((const void*)Ps));
    asm("{ .reg .u64 tt; cvta.to.shared.u64 tt, %1; cvt.u32.u64 %0, tt; }"
        : "=r"(bs_addr) : "l"((const void*)Bs));

    uint32_t a_lane = (uint32_t)((wm * 32 + (l & 7) + 8 * ((l >> 3) & 1)) * SPH
                                 + 4 * (l >> 4)) * 4u;
    uint32_t b_lane = (uint32_t)(((l & 7) + 8 * ((l >> 3) & 1)) * SPH) * 4u
                    + (uint32_t)(wn * 32 + 8 * (l >> 4)) * 2u;

    float acc[2][4][4];
#pragma unroll
    for (int mt = 0; mt < 2; mt++)
#pragma unroll
        for (int nt = 0; nt < 4; nt++)
#pragma unroll
            for (int e = 0; e < 4; e++) acc[mt][nt][e] = 0.f;

    auto stage_B = [&](int jt, int buf) {
#pragma unroll
        for (int m = 0; m < 8; m++) {
            int idx = t + m * 256;
            int j = idx >> 4, ch = idx & 15;
            uint32_t dst = bs_addr + (uint32_t)(buf * BUF * 4 + j * SPH * 4 + ch * 16);
            const void* src = Whb + (long)(jt * 128 + j) * 128 + ch * 8;
            asm volatile("cp.async.cg.shared.global [%0], [%1], 16;" :: "r"(dst), "l"(src));
        }
        asm volatile("cp.async.commit_group;" ::: "memory");
    };

    auto build_P = [&](int jt, int buf) {
        uint32_t* Pb = Ps + buf * BUFP;
        float lsum = 0.f;
        uint32_t mask = mask_sm[i_row * 16 + jt * 4 + (t & 3)];
        const float4* edp = (const float4*)(ed_sm + (jt * 4 + (t & 3)) * 36);
#pragma unroll
        for (int c = 0; c < 8; c++) {
            float4 edv = edp[c];
            float x, p0, p1, p2, p3;
            x = es_i + edv.x; x = fmaxf(x, ALPHA * x); p0 = (mask >> (4 * c))     & 1 ? ex2(x) : 0.f;
            x = es_i + edv.y; x = fmaxf(x, ALPHA * x); p1 = (mask >> (4 * c + 1)) & 1 ? ex2(x) : 0.f;
            x = es_i + edv.z; x = fmaxf(x, ALPHA * x); p2 = (mask >> (4 * c + 2)) & 1 ? ex2(x) : 0.f;
            x = es_i + edv.w; x = fmaxf(x, ALPHA * x); p3 = (mask >> (4 * c + 3)) & 1 ? ex2(x) : 0.f;
            lsum += p0 + p1 + p2 + p3;
            __half2 h01 = __float22half2_rn(make_float2(p0, p1));
            __half2 h23 = __float22half2_rn(make_float2(p2, p3));
            uint2 st;
            st.x = *(uint32_t*)&h01;
            st.y = *(uint32_t*)&h23;
            *(uint2*)&Pb[i_row * SPH + kkb + 2 * c] = st;
        }
        lsum += __shfl_xor_sync(0xffffffffu, lsum, 1);
        lsum += __shfl_xor_sync(0xffffffffu, lsum, 2);
        if ((t & 3) == 0) l_sh[i_row] += lsum;
    };

    auto do_mma = [&](int buf) {
        uint32_t pa = ps_addr + (uint32_t)(buf * BUFP * 4) + a_lane;
        uint32_t ba = bs_addr + (uint32_t)(buf * BUF * 4) + b_lane;
        const uint32_t mt_step = 16 * SPH * 4;
        // B fragments pipelined one kstep ahead.
        uint32_t Bp0[4], Bp1[4];
        LDSM_X4_T(Bp0, ba);
        LDSM_X4_T(Bp1, ba + 32);
#pragma unroll
        for (int ks = 0; ks < 8; ks++) {
            uint32_t A0[4], A1[4];
            LDSM_X4(A0, pa);
            LDSM_X4(A1, pa + mt_step);
            uint32_t B0[4], B1[4];
#pragma unroll
            for (int e = 0; e < 4; e++) { B0[e] = Bp0[e]; B1[e] = Bp1[e]; }
            if (ks < 7) {
                ba += 16 * SPH * 4;     // next k rows
                LDSM_X4_T(Bp0, ba);
                LDSM_X4_T(Bp1, ba + 32);
            }
            uint32_t* Af[2] = {A0, A1};
            uint32_t Bf[4][2] = {{B0[0], B0[1]}, {B0[2], B0[3]},
                                 {B1[0], B1[1]}, {B1[2], B1[3]}};
#pragma unroll
            for (int mt = 0; mt < 2; mt++)
#pragma unroll
                for (int nt = 0; nt < 4; nt++)
                    mma_f16(acc[mt][nt], Af[mt], Bf[nt]);
            pa += 32;               // k += 16 halves
        }
    };

    stage_B(0, 0);
    __syncthreads();   // mask_sm/ed_sm/l_sh visible before first build_P

    build_P(0, 0);
    asm volatile("cp.async.wait_group 0;" ::: "memory");
    __syncthreads();

    for (int jt = 0; jt < 4; jt++) {
        int buf = jt & 1, nbuf = buf ^ 1;
        if (jt < 3) stage_B(jt + 1, nbuf);
        if (w & 1) {
            if (jt < 3) build_P(jt + 1, nbuf);
            do_mma(buf);
        } else {
            do_mma(buf);
            if (jt < 3) build_P(jt + 1, nbuf);
        }
        asm volatile("cp.async.wait_group 0;" ::: "memory");
        __syncthreads();
    }

    // Epilogue: out = acc / l.
#pragma unroll
    for (int mt = 0; mt < 2; mt++) {
        int rb = wm * 32 + mt * 16;
        float inv0 = 1.f / l_sh[rb + gid];
        float inv1 = 1.f / l_sh[rb + gid + 8];
        long row0 = rowbase + ibase + rb + gid;
        long row1 = row0 + 8;
#pragma unroll
        for (int nt = 0; nt < 4; nt++) {
            int col = wn * 32 + nt * 8 + 2 * tig;
            *(float2*)(out + row0 * 128 + col) =
                make_float2(acc[mt][nt][0] * inv0, acc[mt][nt][1] * inv0);
            *(float2*)(out + row1 * 128 + col) =
                make_float2(acc[mt][nt][2] * inv1, acc[mt][nt][3] * inv1);
        }
    }
}

extern "C" void kernel_launch(void* const* d_in, const int* in_sizes, int n_in,
                              void* d_out, int out_size) {
    const float* h   = (const float*)d_in[0];
    const int*   adj = (const int*)d_in[1];
    const float* W   = (const float*)d_in[2];
    const float* a   = (const float*)d_in[3];
    float* out = (float*)d_out;

    int BT = in_sizes[0] / (512 * 128);
    if (BT > 128) BT = 128;

    cudaFuncSetAttribute(gat_wh_mma,
                         cudaFuncAttributeMaxDynamicSharedMemorySize, SMEM_WH);
    cudaFuncSetAttribute(gat_attn_mma,
                         cudaFuncAttributeMaxDynamicSharedMemorySize, SMEM_ATTN);

    gat_wh_mma<<<BT * 4, 512, SMEM_WH>>>(h, W, a, adj);
    gat_attn_mma<<<BT * 8, 256, SMEM_ATTN>>>(out);
}